// round 1
// baseline (speedup 1.0000x reference)
#include <cuda_runtime.h>
#include <math.h>

#define UU 4096   // rows per input
#define PP 1024   // feature dim
#define NT 16     // 1024 / 64 tiles per Gram dimension
#define NPAIR 136 // NT*(NT+1)/2 upper-triangle tile pairs

// Scratch (device globals: no allocation allowed in kernel_launch)
__device__ float g_n1[UU * PP];   // row-normalized input1
__device__ float g_n2[UU * PP];   // row-normalized input2
__device__ float g_S1[PP];        // column sums of g_n1
__device__ float g_S2[PP];        // column sums of g_n2
__device__ float g_cross;         // <G1, G2>_F accumulator

// ---------------------------------------------------------------------------
// init: zero accumulators (must re-zero on every graph replay)
// ---------------------------------------------------------------------------
__global__ void init_k() {
    int i = blockIdx.x * blockDim.x + threadIdx.x;
    if (i < PP)            g_S1[i] = 0.0f;
    else if (i < 2 * PP)   g_S2[i - PP] = 0.0f;
    if (i == 0)            g_cross = 0.0f;
}

// ---------------------------------------------------------------------------
// normalize: one block per row (8192 blocks; first 4096 -> input1)
// n = x / max(||x||, 1e-8)   (matches F.cosine_similarity eps semantics)
// ---------------------------------------------------------------------------
__global__ void __launch_bounds__(256) normalize_k(const float* __restrict__ in1,
                                                   const float* __restrict__ in2) {
    int b = blockIdx.x;
    const float* src;
    float* dst;
    int row;
    if (b < UU) { src = in1; dst = g_n1; row = b; }
    else        { src = in2; dst = g_n2; row = b - UU; }

    float4 v = ((const float4*)(src + (size_t)row * PP))[threadIdx.x];
    float ss = v.x * v.x + v.y * v.y + v.z * v.z + v.w * v.w;

    #pragma unroll
    for (int o = 16; o > 0; o >>= 1)
        ss += __shfl_xor_sync(0xffffffffu, ss, o);

    __shared__ float ws[8];
    int lane = threadIdx.x & 31;
    int w    = threadIdx.x >> 5;
    if (lane == 0) ws[w] = ss;
    __syncthreads();
    if (threadIdx.x < 32) {
        float t = (threadIdx.x < 8) ? ws[threadIdx.x] : 0.0f;
        #pragma unroll
        for (int o = 4; o > 0; o >>= 1)
            t += __shfl_xor_sync(0xffffffffu, t, o);
        if (threadIdx.x == 0) ws[0] = t;
    }
    __syncthreads();

    float inv = 1.0f / fmaxf(sqrtf(ws[0]), 1e-8f);
    ((float4*)(dst + (size_t)row * PP))[threadIdx.x] =
        make_float4(v.x * inv, v.y * inv, v.z * inv, v.w * inv);
}

// ---------------------------------------------------------------------------
// column sums of the normalized matrices.
// grid (8, 8): x = 256-column group across both tensors (2048 virtual cols),
//              y = 512-row chunk. atomicAdd partials into g_S1/g_S2.
// ---------------------------------------------------------------------------
__global__ void __launch_bounds__(256) colsum_k() {
    int c = blockIdx.x * 256 + threadIdx.x;   // 0..2047
    const float* n;
    float* S;
    int col;
    if (c < PP) { n = g_n1; S = g_S1; col = c; }
    else        { n = g_n2; S = g_S2; col = c - PP; }

    int u0 = blockIdx.y * (UU / 8);
    float s0 = 0.f, s1 = 0.f, s2 = 0.f, s3 = 0.f;
    for (int u = u0; u < u0 + UU / 8; u += 4) {
        s0 += n[(size_t)(u + 0) * PP + col];
        s1 += n[(size_t)(u + 1) * PP + col];
        s2 += n[(size_t)(u + 2) * PP + col];
        s3 += n[(size_t)(u + 3) * PP + col];
    }
    atomicAdd(&S[col], (s0 + s1) + (s2 + s3));
}

// ---------------------------------------------------------------------------
// Fused Gram cross-dot: each block owns one upper-triangle 64x64 tile pair
// (pt<=qt) of BOTH Grams G1 = n1^T n1 and G2 = n2^T n2, K = 4096.
// After the K loop it dots the two tiles elementwise (off-diag tiles
// weighted x2 by symmetry) and atomicAdds into g_cross.
// 256 threads, 4x4 register micro-tile per thread per Gram, register-staged
// global prefetch to hide load latency under FMA.
// ---------------------------------------------------------------------------
__global__ void __launch_bounds__(256) gram_k() {
    int b = blockIdx.x;
    int pt = 0, rem = b;
    while (rem >= NT - pt) { rem -= NT - pt; pt++; }
    int qt = pt + rem;
    int p0 = pt * 64, q0 = qt * 64;

    __shared__ float sA1[16][64];  // n1 cols [p0, p0+64)
    __shared__ float sB1[16][64];  // n1 cols [q0, q0+64)
    __shared__ float sA2[16][64];  // n2 cols [p0, p0+64)
    __shared__ float sB2[16][64];  // n2 cols [q0, q0+64)

    int tid = threadIdx.x;
    int tx  = tid & 15;        // q direction (4 cols each)
    int ty  = tid >> 4;        // p direction (4 rows each)
    int lr  = tid >> 4;        // staging: k row 0..15
    int lc  = (tid & 15) * 4;  // staging: col offset (float4)

    float acc1[4][4], acc2[4][4];
    #pragma unroll
    for (int i = 0; i < 4; i++)
        #pragma unroll
        for (int j = 0; j < 4; j++) { acc1[i][j] = 0.f; acc2[i][j] = 0.f; }

    // prefetch first chunk into registers
    size_t base = (size_t)lr * PP;
    float4 rA1 = *(const float4*)&g_n1[base + p0 + lc];
    float4 rB1 = *(const float4*)&g_n1[base + q0 + lc];
    float4 rA2 = *(const float4*)&g_n2[base + p0 + lc];
    float4 rB2 = *(const float4*)&g_n2[base + q0 + lc];

    for (int k0 = 0; k0 < UU; k0 += 16) {
        *(float4*)&sA1[lr][lc] = rA1;
        *(float4*)&sB1[lr][lc] = rB1;
        *(float4*)&sA2[lr][lc] = rA2;
        *(float4*)&sB2[lr][lc] = rB2;
        __syncthreads();

        if (k0 + 16 < UU) {   // prefetch next chunk while computing
            size_t nb = (size_t)(k0 + 16 + lr) * PP;
            rA1 = *(const float4*)&g_n1[nb + p0 + lc];
            rB1 = *(const float4*)&g_n1[nb + q0 + lc];
            rA2 = *(const float4*)&g_n2[nb + p0 + lc];
            rB2 = *(const float4*)&g_n2[nb + q0 + lc];
        }

        #pragma unroll
        for (int kk = 0; kk < 16; kk++) {
            float4 a1 = *(const float4*)&sA1[kk][ty * 4];
            float4 b1 = *(const float4*)&sB1[kk][tx * 4];
            float4 a2 = *(const float4*)&sA2[kk][ty * 4];
            float4 b2 = *(const float4*)&sB2[kk][tx * 4];
            float av1[4] = {a1.x, a1.y, a1.z, a1.w};
            float bv1[4] = {b1.x, b1.y, b1.z, b1.w};
            float av2[4] = {a2.x, a2.y, a2.z, a2.w};
            float bv2[4] = {b2.x, b2.y, b2.z, b2.w};
            #pragma unroll
            for (int i = 0; i < 4; i++)
                #pragma unroll
                for (int j = 0; j < 4; j++) {
                    acc1[i][j] = fmaf(av1[i], bv1[j], acc1[i][j]);
                    acc2[i][j] = fmaf(av2[i], bv2[j], acc2[i][j]);
                }
        }
        __syncthreads();
    }

    // per-thread elementwise dot of the two Gram tiles
    float d = 0.f;
    #pragma unroll
    for (int i = 0; i < 4; i++)
        #pragma unroll
        for (int j = 0; j < 4; j++)
            d += acc1[i][j] * acc2[i][j];

    #pragma unroll
    for (int o = 16; o > 0; o >>= 1)
        d += __shfl_xor_sync(0xffffffffu, d, o);

    __shared__ float rs[8];
    int lane = tid & 31, wp = tid >> 5;
    if (lane == 0) rs[wp] = d;
    __syncthreads();
    if (tid == 0) {
        float t = 0.f;
        #pragma unroll
        for (int i = 0; i < 8; i++) t += rs[i];
        float wgt = (pt == qt) ? 1.0f : 2.0f;   // symmetry: off-diag tiles count twice
        atomicAdd(&g_cross, wgt * t);
    }
}

// ---------------------------------------------------------------------------
// finalize: loss = U*V - 2 * (S1 . S2) + <G1, G2>_F
// ---------------------------------------------------------------------------
__global__ void __launch_bounds__(256) finalize_k(float* __restrict__ out) {
    int t = threadIdx.x;
    float s = 0.f;
    for (int c = t; c < PP; c += 256)
        s += g_S1[c] * g_S2[c];
    #pragma unroll
    for (int o = 16; o > 0; o >>= 1)
        s += __shfl_xor_sync(0xffffffffu, s, o);
    __shared__ float ws[8];
    if ((t & 31) == 0) ws[t >> 5] = s;
    __syncthreads();
    if (t == 0) {
        float dot = 0.f;
        #pragma unroll
        for (int i = 0; i < 8; i++) dot += ws[i];
        double loss = 16777216.0   // U*V = 4096*4096
                    - 2.0 * (double)dot
                    + (double)g_cross;
        out[0] = (float)loss;
    }
}

// ---------------------------------------------------------------------------
extern "C" void kernel_launch(void* const* d_in, const int* in_sizes, int n_in,
                              void* d_out, int out_size) {
    const float* in1 = (const float*)d_in[0];
    const float* in2 = (const float*)d_in[1];
    float* out = (float*)d_out;

    init_k<<<8, 256>>>();
    normalize_k<<<2 * UU, 256>>>(in1, in2);
    colsum_k<<<dim3(8, 8), 256>>>();
    gram_k<<<NPAIR, 256>>>();
    finalize_k<<<1, 256>>>(out);
}

// round 3
// speedup vs baseline: 4.2297x; 4.2297x over previous
#include <cuda_runtime.h>
#include <cuda_bf16.h>
#include <cstdint>
#include <math.h>

#define UU 4096   // rows (K of the Gram)
#define PP 1024   // feature dim (M=N of the Gram)
#define NTILE 8   // 1024/128 tiles per Gram dim
#define NPAIR 36  // upper-triangle tile pairs
#define KC 64     // K per pipeline chunk
#define KHALF 2048
#define NCHUNK (KHALF / KC)        // 32
#define TILE_BYTES 16384           // 128 rows x 64 bf16 x 2B
#define STAGE_BYTES (2 * TILE_BYTES)
#define GRAM_SMEM (2 * STAGE_BYTES + 256)   // 2 stages + align slack

// ---- scratch (device globals; no runtime allocation allowed) ----
__device__ __nv_bfloat16 g_b1T[PP * UU];  // normalized input1, transposed [c][k]
__device__ __nv_bfloat16 g_b2T[PP * UU];  // normalized input2, transposed [c][k]
__device__ float g_inv[2 * UU];           // per-row 1/max(norm,eps)
__device__ float g_S[2 * PP];             // column sums
__device__ float g_G[2 * 2 * NPAIR * 128 * 128]; // [gram][khalf][pair][128][128]
__device__ float g_cross;

// ============================ helpers =======================================
__device__ __forceinline__ uint32_t smem_u32(const void* p) {
    uint32_t a;
    asm("{ .reg .u64 t; cvta.to.shared.u64 t, %1; cvt.u32.u64 %0, t; }" : "=r"(a) : "l"(p));
    return a;
}
__device__ __forceinline__ void sts128(uint32_t addr, uint4 v) {
    asm volatile("st.shared.v4.b32 [%0], {%1, %2, %3, %4};"
                 :: "r"(addr), "r"(v.x), "r"(v.y), "r"(v.z), "r"(v.w) : "memory");
}
__device__ __forceinline__ void ldsm_x4(uint32_t& r0, uint32_t& r1, uint32_t& r2, uint32_t& r3,
                                        uint32_t addr) {
    asm volatile("ldmatrix.sync.aligned.m8n8.x4.shared.b16 {%0, %1, %2, %3}, [%4];"
                 : "=r"(r0), "=r"(r1), "=r"(r2), "=r"(r3) : "r"(addr));
}
__device__ __forceinline__ void mma16816(float* c, uint32_t a0, uint32_t a1, uint32_t a2,
                                         uint32_t a3, uint32_t b0, uint32_t b1) {
    asm volatile(
        "mma.sync.aligned.m16n8k16.row.col.f32.bf16.bf16.f32 "
        "{%0, %1, %2, %3}, {%4, %5, %6, %7}, {%8, %9}, {%0, %1, %2, %3};"
        : "+f"(c[0]), "+f"(c[1]), "+f"(c[2]), "+f"(c[3])
        : "r"(a0), "r"(a1), "r"(a2), "r"(a3), "r"(b0), "r"(b1));
}

// ============================ kernels =======================================
__global__ void init_k() { if (threadIdx.x == 0) g_cross = 0.0f; }

// per-row inverse norms (fp32)
__global__ void __launch_bounds__(256) norm_k(const float* __restrict__ in1,
                                              const float* __restrict__ in2) {
    int b = blockIdx.x;                       // 0..8191
    const float* src = (b < UU) ? in1 : in2;
    int row = b & (UU - 1);
    float4 v = ((const float4*)(src + (size_t)row * PP))[threadIdx.x];
    float ss = v.x * v.x + v.y * v.y + v.z * v.z + v.w * v.w;
    #pragma unroll
    for (int o = 16; o > 0; o >>= 1) ss += __shfl_xor_sync(0xffffffffu, ss, o);
    __shared__ float ws[8];
    if ((threadIdx.x & 31) == 0) ws[threadIdx.x >> 5] = ss;
    __syncthreads();
    if (threadIdx.x == 0) {
        float t = ws[0] + ws[1] + ws[2] + ws[3] + ws[4] + ws[5] + ws[6] + ws[7];
        g_inv[b] = 1.0f / fmaxf(sqrtf(t), 1e-8f);
    }
}

// fused scale + bf16 convert + transpose (64x64 tiles)
__global__ void __launch_bounds__(256) conv_k(const float* __restrict__ in1,
                                              const float* __restrict__ in2) {
    int mat = blockIdx.z;
    const float* src = mat ? in2 : in1;
    __nv_bfloat16* dst = mat ? g_b2T : g_b1T;
    int c0 = blockIdx.x * 64, k0 = blockIdx.y * 64;
    __shared__ float s[64][65];
    int tid = threadIdx.x;
    #pragma unroll
    for (int r = 0; r < 4; r++) {
        int li = r * 256 + tid;
        int k = li >> 4, c4 = (li & 15) << 2;
        float4 v = *(const float4*)&src[(size_t)(k0 + k) * PP + c0 + c4];
        float inv = g_inv[mat * UU + k0 + k];
        s[c4 + 0][k] = v.x * inv; s[c4 + 1][k] = v.y * inv;
        s[c4 + 2][k] = v.z * inv; s[c4 + 3][k] = v.w * inv;
    }
    __syncthreads();
    int c = tid >> 2, kg = (tid & 3) << 4;
    uint32_t pk[8];
    #pragma unroll
    for (int t = 0; t < 8; t++) {
        __nv_bfloat162 b = __floats2bfloat162_rn(s[c][kg + 2 * t], s[c][kg + 2 * t + 1]);
        pk[t] = *(uint32_t*)&b;
    }
    uint4* outp = (uint4*)&dst[(size_t)(c0 + c) * UU + k0 + kg];
    outp[0] = make_uint4(pk[0], pk[1], pk[2], pk[3]);
    outp[1] = make_uint4(pk[4], pk[5], pk[6], pk[7]);
}

// column sums (= row sums of transposed bf16)
__global__ void __launch_bounds__(256) colsum_k() {
    int rowg = blockIdx.x;                    // 0..2047
    const __nv_bfloat16* src = (rowg < PP) ? g_b1T : g_b2T;
    const uint4* p = (const uint4*)(src + (size_t)(rowg & (PP - 1)) * UU);
    int tid = threadIdx.x;
    float s = 0.f;
    #pragma unroll
    for (int r = 0; r < 2; r++) {
        uint4 u = p[tid + r * 256];
        uint32_t w[4] = {u.x, u.y, u.z, u.w};
        #pragma unroll
        for (int i = 0; i < 4; i++) {
            float2 f = __bfloat1622float2(*(__nv_bfloat162*)&w[i]);
            s += f.x + f.y;
        }
    }
    #pragma unroll
    for (int o = 16; o > 0; o >>= 1) s += __shfl_xor_sync(0xffffffffu, s, o);
    __shared__ float ws[8];
    if ((tid & 31) == 0) ws[tid >> 5] = s;
    __syncthreads();
    if (tid == 0)
        g_S[rowg] = ws[0] + ws[1] + ws[2] + ws[3] + ws[4] + ws[5] + ws[6] + ws[7];
}

// HMMA Gram kernel: grid 144 = 2 grams x 36 pairs x 2 K-halves.
// CTA tile 128x128, warp tile 64x32 (warps 2x4), K-chunk 64, double-buffered smem.
__global__ void __launch_bounds__(256, 1) gram_k() {
    extern __shared__ char dyn[];
    int b = blockIdx.x;
    int g = (b >= 72); int r0_ = b - g * 72;
    int h = (r0_ >= NPAIR); int pair = r0_ - h * NPAIR;
    int pt = 0, rem = pair;
    while (rem >= NTILE - pt) { rem -= NTILE - pt; pt++; }
    int qt = pt + rem;

    const __nv_bfloat16* src = g ? g_b2T : g_b1T;
    const uint4* PA = (const uint4*)src + (size_t)(pt * 128) * 512 + h * 256; // 512 uint4/row
    const uint4* PB = (const uint4*)src + (size_t)(qt * 128) * 512 + h * 256;

    int tid = threadIdx.x;
    uint32_t sbase = (smem_u32(dyn) + 127u) & ~127u;

    // loader mapping: 4 uint4 per thread per matrix per chunk
    int gidx[4]; uint32_t soff[4];
    #pragma unroll
    for (int r = 0; r < 4; r++) {
        int li = r * 256 + tid;
        int m = li >> 3, c = li & 7;
        gidx[r] = m * 512 + c;
        soff[r] = (uint32_t)(m * 128 + ((c ^ (m & 7)) << 4));
    }

    // compute-side constants
    int wid = tid >> 5, lane = tid & 31;
    int wm = wid >> 2, wn = wid & 3;          // warp grid 2(m) x 4(n)
    int m_base = wm * 64, n_base = wn * 32;
    int lrow = lane & 15, lcol = lane >> 4;
    uint32_t offA[4], swA[4], offB[2], swB[2];
    #pragma unroll
    for (int mt = 0; mt < 4; mt++) {
        int rw = m_base + mt * 16 + lrow;
        offA[mt] = (uint32_t)(rw * 128); swA[mt] = (uint32_t)(rw & 7);
    }
    #pragma unroll
    for (int nt2 = 0; nt2 < 2; nt2++) {
        int rw = n_base + nt2 * 16 + lrow;
        offB[nt2] = (uint32_t)(rw * 128); swB[nt2] = (uint32_t)(rw & 7);
    }

    float acc[4][4][4];
    #pragma unroll
    for (int i = 0; i < 4; i++)
        #pragma unroll
        for (int j = 0; j < 4; j++)
            #pragma unroll
            for (int k = 0; k < 4; k++) acc[i][j][k] = 0.f;

    uint4 ra[4], rb[4];
    #pragma unroll
    for (int r = 0; r < 4; r++) { ra[r] = PA[gidx[r]]; rb[r] = PB[gidx[r]]; }

    for (int ch = 0; ch < NCHUNK; ch++) {
        uint32_t sA = sbase + (uint32_t)((ch & 1) * STAGE_BYTES);
        uint32_t sB = sA + TILE_BYTES;
        #pragma unroll
        for (int r = 0; r < 4; r++) {
            sts128(sA + soff[r], ra[r]);
            sts128(sB + soff[r], rb[r]);
        }
        __syncthreads();
        if (ch + 1 < NCHUNK) {
            int k4 = (ch + 1) * 8;
            #pragma unroll
            for (int r = 0; r < 4; r++) {
                ra[r] = PA[gidx[r] + k4];
                rb[r] = PB[gidx[r] + k4];
            }
        }
        #pragma unroll
        for (int kk = 0; kk < 4; kk++) {
            uint32_t cbase = (uint32_t)(2 * kk + lcol);
            uint32_t bf[2][4];
            #pragma unroll
            for (int nt2 = 0; nt2 < 2; nt2++)
                ldsm_x4(bf[nt2][0], bf[nt2][1], bf[nt2][2], bf[nt2][3],
                        sB + offB[nt2] + (((cbase ^ swB[nt2]) & 7u) << 4));
            #pragma unroll
            for (int mt = 0; mt < 4; mt++) {
                uint32_t a0, a1, a2, a3;
                ldsm_x4(a0, a1, a2, a3,
                        sA + offA[mt] + (((cbase ^ swA[mt]) & 7u) << 4));
                // nt tiles 0..3: (nt2 = nt>>1, within: b0 = f[0|1], b1 = f[2|3])
                mma16816(acc[mt][0], a0, a1, a2, a3, bf[0][0], bf[0][2]);
                mma16816(acc[mt][1], a0, a1, a2, a3, bf[0][1], bf[0][3]);
                mma16816(acc[mt][2], a0, a1, a2, a3, bf[1][0], bf[1][2]);
                mma16816(acc[mt][3], a0, a1, a2, a3, bf[1][1], bf[1][3]);
            }
        }
        __syncthreads();
    }

    // epilogue: store raw 128x128 fp32 tile
    float* out = g_G + ((size_t)((g * 2 + h) * NPAIR + pair) << 14);
    int er = lane >> 2, ec = (lane & 3) << 1;
    #pragma unroll
    for (int mt = 0; mt < 4; mt++)
        #pragma unroll
        for (int nt = 0; nt < 4; nt++) {
            int row = m_base + mt * 16 + er;
            int col = n_base + nt * 8 + ec;
            *(float2*)&out[row * 128 + col]       = make_float2(acc[mt][nt][0], acc[mt][nt][1]);
            *(float2*)&out[(row + 8) * 128 + col] = make_float2(acc[mt][nt][2], acc[mt][nt][3]);
        }
}

// cross = sum over tile pairs of weight * (G1h0+G1h1) .* (G2h0+G2h1)
__global__ void __launch_bounds__(256) dot_k() {
    int pair = blockIdx.x;
    int pt = 0, rem = pair;
    while (rem >= NTILE - pt) { rem -= NTILE - pt; pt++; }
    float w = (rem == 0) ? 1.0f : 2.0f;

    const float4* a0 = (const float4*)(g_G + ((size_t)(0 * NPAIR + pair) << 14));
    const float4* a1 = (const float4*)(g_G + ((size_t)(1 * NPAIR + pair) << 14));
    const float4* b0 = (const float4*)(g_G + ((size_t)(2 * NPAIR + pair) << 14));
    const float4* b1 = (const float4*)(g_G + ((size_t)(3 * NPAIR + pair) << 14));
    int tid = threadIdx.x;
    float s = 0.f;
    for (int i = tid; i < 4096; i += 256) {
        float4 xa = a0[i], xb = a1[i], ya = b0[i], yb = b1[i];
        s += (xa.x + xb.x) * (ya.x + yb.x) + (xa.y + xb.y) * (ya.y + yb.y)
           + (xa.z + xb.z) * (ya.z + yb.z) + (xa.w + xb.w) * (ya.w + yb.w);
    }
    #pragma unroll
    for (int o = 16; o > 0; o >>= 1) s += __shfl_xor_sync(0xffffffffu, s, o);
    __shared__ float ws[8];
    if ((tid & 31) == 0) ws[tid >> 5] = s;
    __syncthreads();
    if (tid == 0) {
        float t = ws[0] + ws[1] + ws[2] + ws[3] + ws[4] + ws[5] + ws[6] + ws[7];
        atomicAdd(&g_cross, w * t);
    }
}

// loss = U*V - 2*(S1 . S2) + cross
__global__ void __launch_bounds__(256) finalize_k(float* __restrict__ out) {
    int tid = threadIdx.x;
    float s = 0.f;
    #pragma unroll
    for (int r = 0; r < 4; r++) {
        int c = tid + r * 256;
        s += g_S[c] * g_S[PP + c];
    }
    #pragma unroll
    for (int o = 16; o > 0; o >>= 1) s += __shfl_xor_sync(0xffffffffu, s, o);
    __shared__ float ws[8];
    if ((tid & 31) == 0) ws[tid >> 5] = s;
    __syncthreads();
    if (tid == 0) {
        float dot = ws[0] + ws[1] + ws[2] + ws[3] + ws[4] + ws[5] + ws[6] + ws[7];
        double loss = 16777216.0 - 2.0 * (double)dot + (double)g_cross;
        out[0] = (float)loss;
    }
}

// ============================================================================
extern "C" void kernel_launch(void* const* d_in, const int* in_sizes, int n_in,
                              void* d_out, int out_size) {
    const float* in1 = (const float*)d_in[0];
    const float* in2 = (const float*)d_in[1];
    float* out = (float*)d_out;

    static int configured = 0;
    if (!configured) {
        cudaFuncSetAttribute(gram_k, cudaFuncAttributeMaxDynamicSharedMemorySize, GRAM_SMEM);
        configured = 1;
    }

    init_k<<<1, 32>>>();
    norm_k<<<2 * UU, 256>>>(in1, in2);
    conv_k<<<dim3(PP / 64, UU / 64, 2), 256>>>(in1, in2);
    colsum_k<<<2 * PP, 256>>>();
    gram_k<<<144, 256, GRAM_SMEM>>>();
    dot_k<<<NPAIR, 256>>>();
    finalize_k<<<1, 256>>>(out);
}

// round 4
// speedup vs baseline: 4.9574x; 1.1720x over previous
#include <cuda_runtime.h>
#include <cuda_bf16.h>
#include <cstdint>
#include <math.h>

#define UU 4096   // rows (K of the Gram)
#define PP 1024   // feature dim (M=N of the Gram)
#define NTILE 8   // 1024/128 tiles per Gram dim
#define NPAIR 36  // upper-triangle tile pairs
#define KC 64     // K per pipeline chunk
#define KHALF 2048
#define NCHUNK (KHALF / KC)        // 32
#define TILE_BYTES 16384           // 128 rows x 64 bf16 x 2B
#define STAGE_BYTES (2 * TILE_BYTES)
#define NST 4
#define GRAM_SMEM (NST * STAGE_BYTES + 256)

// ---- scratch (device globals; no runtime allocation allowed) ----
__device__ __nv_bfloat16 g_b1T[PP * UU];  // normalized input1, transposed [c][k]
__device__ __nv_bfloat16 g_b2T[PP * UU];  // normalized input2, transposed [c][k]
__device__ float g_inv[2 * UU];           // per-row 1/max(norm,eps)
__device__ float g_S[2 * PP];             // column sums (atomic accumulated)
__device__ float g_G[2 * 2 * NPAIR * 128 * 128]; // [gram*2+khalf][pair][128][128]
__device__ float g_cross;

// ============================ helpers =======================================
__device__ __forceinline__ uint32_t smem_u32(const void* p) {
    uint32_t a;
    asm("{ .reg .u64 t; cvta.to.shared.u64 t, %1; cvt.u32.u64 %0, t; }" : "=r"(a) : "l"(p));
    return a;
}
__device__ __forceinline__ void cp_async16(uint32_t sdst, const void* gsrc) {
    asm volatile("cp.async.cg.shared.global [%0], [%1], 16;" :: "r"(sdst), "l"(gsrc) : "memory");
}
__device__ __forceinline__ void cp_commit() {
    asm volatile("cp.async.commit_group;" ::: "memory");
}
__device__ __forceinline__ void ldsm_x4(uint32_t& r0, uint32_t& r1, uint32_t& r2, uint32_t& r3,
                                        uint32_t addr) {
    asm volatile("ldmatrix.sync.aligned.m8n8.x4.shared.b16 {%0, %1, %2, %3}, [%4];"
                 : "=r"(r0), "=r"(r1), "=r"(r2), "=r"(r3) : "r"(addr));
}
__device__ __forceinline__ void mma16816(float* c, uint32_t a0, uint32_t a1, uint32_t a2,
                                         uint32_t a3, uint32_t b0, uint32_t b1) {
    asm volatile(
        "mma.sync.aligned.m16n8k16.row.col.f32.bf16.bf16.f32 "
        "{%0, %1, %2, %3}, {%4, %5, %6, %7}, {%8, %9}, {%0, %1, %2, %3};"
        : "+f"(c[0]), "+f"(c[1]), "+f"(c[2]), "+f"(c[3])
        : "r"(a0), "r"(a1), "r"(a2), "r"(a3), "r"(b0), "r"(b1));
}

// ============================ kernels =======================================
__global__ void init_k() {
    int i = blockIdx.x * blockDim.x + threadIdx.x;
    if (i < 2 * PP) g_S[i] = 0.0f;
    if (i == 0) g_cross = 0.0f;
}

// per-row inverse norms (fp32)
__global__ void __launch_bounds__(256) norm_k(const float* __restrict__ in1,
                                              const float* __restrict__ in2) {
    int b = blockIdx.x;                       // 0..8191
    const float* src = (b < UU) ? in1 : in2;
    int row = b & (UU - 1);
    float4 v = ((const float4*)(src + (size_t)row * PP))[threadIdx.x];
    float ss = v.x * v.x + v.y * v.y + v.z * v.z + v.w * v.w;
    #pragma unroll
    for (int o = 16; o > 0; o >>= 1) ss += __shfl_xor_sync(0xffffffffu, ss, o);
    __shared__ float ws[8];
    if ((threadIdx.x & 31) == 0) ws[threadIdx.x >> 5] = ss;
    __syncthreads();
    if (threadIdx.x == 0) {
        float t = ws[0] + ws[1] + ws[2] + ws[3] + ws[4] + ws[5] + ws[6] + ws[7];
        g_inv[b] = 1.0f / fmaxf(sqrtf(t), 1e-8f);
    }
}

// fused scale + bf16 convert + transpose (64x64 tiles) + partial column sums
__global__ void __launch_bounds__(256) conv_k(const float* __restrict__ in1,
                                              const float* __restrict__ in2) {
    int mat = blockIdx.z;
    const float* src = mat ? in2 : in1;
    __nv_bfloat16* dst = mat ? g_b2T : g_b1T;
    int c0 = blockIdx.x * 64, k0 = blockIdx.y * 64;
    __shared__ float s[64][65];
    int tid = threadIdx.x;
    #pragma unroll
    for (int r = 0; r < 4; r++) {
        int li = r * 256 + tid;
        int k = li >> 4, c4 = (li & 15) << 2;
        float4 v = *(const float4*)&src[(size_t)(k0 + k) * PP + c0 + c4];
        float inv = g_inv[mat * UU + k0 + k];
        s[c4 + 0][k] = v.x * inv; s[c4 + 1][k] = v.y * inv;
        s[c4 + 2][k] = v.z * inv; s[c4 + 3][k] = v.w * inv;
    }
    __syncthreads();
    // pack + transpose store
    int c = tid >> 2, kg = (tid & 3) << 4;
    uint32_t pk[8];
    #pragma unroll
    for (int t = 0; t < 8; t++) {
        __nv_bfloat162 b = __floats2bfloat162_rn(s[c][kg + 2 * t], s[c][kg + 2 * t + 1]);
        pk[t] = *(uint32_t*)&b;
    }
    uint4* outp = (uint4*)&dst[(size_t)(c0 + c) * UU + k0 + kg];
    outp[0] = make_uint4(pk[0], pk[1], pk[2], pk[3]);
    outp[1] = make_uint4(pk[4], pk[5], pk[6], pk[7]);
    // fused partial column sums (fp32 normalized values)
    float cs = 0.f;
    #pragma unroll
    for (int i = 0; i < 16; i++) cs += s[c][kg + i];
    cs += __shfl_xor_sync(0xffffffffu, cs, 1);
    cs += __shfl_xor_sync(0xffffffffu, cs, 2);
    if ((tid & 3) == 0) atomicAdd(&g_S[mat * PP + c0 + c], cs);
}

// HMMA Gram kernel: grid 144 = 2 grams x 36 pairs x 2 K-halves.
// CTA tile 128x128, 4 warps (2x2), warp tile 64x64, cp.async 4-stage pipeline.
__global__ void __launch_bounds__(128, 1) gram_k() {
    extern __shared__ char dyn[];
    int b = blockIdx.x;
    int g = (b >= 72); int r0_ = b - g * 72;
    int h = (r0_ >= NPAIR); int pair = r0_ - h * NPAIR;
    int pt = 0, rem = pair;
    while (rem >= NTILE - pt) { rem -= NTILE - pt; pt++; }
    int qt = pt + rem;

    const __nv_bfloat16* src = g ? g_b2T : g_b1T;
    const uint4* PA = (const uint4*)src + (size_t)(pt * 128) * 512 + h * 256; // 512 uint4/row
    const uint4* PB = (const uint4*)src + (size_t)(qt * 128) * 512 + h * 256;

    int tid = threadIdx.x;
    uint32_t sbase = (smem_u32(dyn) + 127u) & ~127u;

    // loader mapping: thread -> (m0 = tid>>3, c0 = tid&7); r adds 16 rows
    int m0 = tid >> 3, cc0 = tid & 7;
    int gbase = m0 * 512 + cc0;                           // uint4 index
    uint32_t sbo = (uint32_t)(m0 * 128 + ((cc0 ^ (m0 & 7)) << 4));

    // compute-side constants
    int wid = tid >> 5, lane = tid & 31;
    int wm = wid >> 1, wn = wid & 1;          // warp grid 2(m) x 2(n)
    int m_base = wm * 64, n_base = wn * 64;
    int lrow = lane & 15, lcol = lane >> 4;
    uint32_t offA[4], swA[4], offB[4], swB[4];
    #pragma unroll
    for (int t = 0; t < 4; t++) {
        int rwa = m_base + t * 16 + lrow;
        offA[t] = (uint32_t)(rwa * 128); swA[t] = (uint32_t)(rwa & 7);
        int rwb = n_base + t * 16 + lrow;
        offB[t] = (uint32_t)(rwb * 128); swB[t] = (uint32_t)(rwb & 7);
    }

    float acc[4][8][4];
    #pragma unroll
    for (int i = 0; i < 4; i++)
        #pragma unroll
        for (int j = 0; j < 8; j++)
            #pragma unroll
            for (int k = 0; k < 4; k++) acc[i][j][k] = 0.f;

    // prologue: load chunks 0..2 into stages 0..2
    #pragma unroll
    for (int s = 0; s < 3; s++) {
        uint32_t sA = sbase + (uint32_t)(s * STAGE_BYTES);
        uint32_t sB = sA + TILE_BYTES;
        int k4 = s * 8;
        #pragma unroll
        for (int r = 0; r < 8; r++) {
            cp_async16(sA + sbo + r * 2048, PA + gbase + r * 8192 + k4);
            cp_async16(sB + sbo + r * 2048, PB + gbase + r * 8192 + k4);
        }
        cp_commit();
    }

    for (int ch = 0; ch < NCHUNK; ch++) {
        asm volatile("cp.async.wait_group 2;" ::: "memory");
        __syncthreads();
        if (ch + 3 < NCHUNK) {
            int st = (ch + 3) & (NST - 1);
            uint32_t sA = sbase + (uint32_t)(st * STAGE_BYTES);
            uint32_t sB = sA + TILE_BYTES;
            int k4 = (ch + 3) * 8;
            #pragma unroll
            for (int r = 0; r < 8; r++) {
                cp_async16(sA + sbo + r * 2048, PA + gbase + r * 8192 + k4);
                cp_async16(sB + sbo + r * 2048, PB + gbase + r * 8192 + k4);
            }
            cp_commit();
        }
        uint32_t sA = sbase + (uint32_t)((ch & (NST - 1)) * STAGE_BYTES);
        uint32_t sB = sA + TILE_BYTES;
        #pragma unroll
        for (int kk = 0; kk < 4; kk++) {
            uint32_t cbase = (uint32_t)(2 * kk + lcol);
            uint32_t bf[4][4];
            #pragma unroll
            for (int nt2 = 0; nt2 < 4; nt2++)
                ldsm_x4(bf[nt2][0], bf[nt2][1], bf[nt2][2], bf[nt2][3],
                        sB + offB[nt2] + (((cbase ^ swB[nt2]) & 7u) << 4));
            #pragma unroll
            for (int mt = 0; mt < 4; mt++) {
                uint32_t a0, a1, a2, a3;
                ldsm_x4(a0, a1, a2, a3,
                        sA + offA[mt] + (((cbase ^ swA[mt]) & 7u) << 4));
                #pragma unroll
                for (int nt2 = 0; nt2 < 4; nt2++) {
                    mma16816(acc[mt][2 * nt2 + 0], a0, a1, a2, a3, bf[nt2][0], bf[nt2][2]);
                    mma16816(acc[mt][2 * nt2 + 1], a0, a1, a2, a3, bf[nt2][1], bf[nt2][3]);
                }
            }
        }
    }

    // epilogue: store raw 128x128 fp32 tile
    float* out = g_G + ((size_t)((g * 2 + h) * NPAIR + pair) << 14);
    int er = lane >> 2, ec = (lane & 3) << 1;
    #pragma unroll
    for (int mt = 0; mt < 4; mt++)
        #pragma unroll
        for (int nt = 0; nt < 8; nt++) {
            int row = m_base + mt * 16 + er;
            int col = n_base + nt * 8 + ec;
            *(float2*)&out[row * 128 + col]       = make_float2(acc[mt][nt][0], acc[mt][nt][1]);
            *(float2*)&out[(row + 8) * 128 + col] = make_float2(acc[mt][nt][2], acc[mt][nt][3]);
        }
}

// cross = sum over tile pairs of weight * (G1h0+G1h1) .* (G2h0+G2h1)
__global__ void __launch_bounds__(256) dot_k() {
    int pair = blockIdx.x;
    int pt = 0, rem = pair;
    while (rem >= NTILE - pt) { rem -= NTILE - pt; pt++; }
    float w = (rem == 0) ? 1.0f : 2.0f;

    const float4* a0 = (const float4*)(g_G + ((size_t)(0 * NPAIR + pair) << 14));
    const float4* a1 = (const float4*)(g_G + ((size_t)(1 * NPAIR + pair) << 14));
    const float4* b0 = (const float4*)(g_G + ((size_t)(2 * NPAIR + pair) << 14));
    const float4* b1 = (const float4*)(g_G + ((size_t)(3 * NPAIR + pair) << 14));
    int tid = threadIdx.x;
    float s = 0.f;
    for (int i = tid; i < 4096; i += 256) {
        float4 xa = a0[i], xb = a1[i], ya = b0[i], yb = b1[i];
        s += (xa.x + xb.x) * (ya.x + yb.x) + (xa.y + xb.y) * (ya.y + yb.y)
           + (xa.z + xb.z) * (ya.z + yb.z) + (xa.w + xb.w) * (ya.w + yb.w);
    }
    #pragma unroll
    for (int o = 16; o > 0; o >>= 1) s += __shfl_xor_sync(0xffffffffu, s, o);
    __shared__ float ws[8];
    if ((tid & 31) == 0) ws[tid >> 5] = s;
    __syncthreads();
    if (tid == 0) {
        float t = ws[0] + ws[1] + ws[2] + ws[3] + ws[4] + ws[5] + ws[6] + ws[7];
        atomicAdd(&g_cross, w * t);
    }
}

// loss = U*V - 2*(S1 . S2) + cross
__global__ void __launch_bounds__(256) finalize_k(float* __restrict__ out) {
    int tid = threadIdx.x;
    float s = 0.f;
    #pragma unroll
    for (int r = 0; r < 4; r++) {
        int c = tid + r * 256;
        s += g_S[c] * g_S[PP + c];
    }
    #pragma unroll
    for (int o = 16; o > 0; o >>= 1) s += __shfl_xor_sync(0xffffffffu, s, o);
    __shared__ float ws[8];
    if ((tid & 31) == 0) ws[tid >> 5] = s;
    __syncthreads();
    if (tid == 0) {
        float dot = ws[0] + ws[1] + ws[2] + ws[3] + ws[4] + ws[5] + ws[6] + ws[7];
        double loss = 16777216.0 - 2.0 * (double)dot + (double)g_cross;
        out[0] = (float)loss;
    }
}

// ============================================================================
extern "C" void kernel_launch(void* const* d_in, const int* in_sizes, int n_in,
                              void* d_out, int out_size) {
    const float* in1 = (const float*)d_in[0];
    const float* in2 = (const float*)d_in[1];
    float* out = (float*)d_out;

    cudaFuncSetAttribute(gram_k, cudaFuncAttributeMaxDynamicSharedMemorySize, GRAM_SMEM);

    init_k<<<8, 256>>>();
    norm_k<<<2 * UU, 256>>>(in1, in2);
    conv_k<<<dim3(PP / 64, UU / 64, 2), 256>>>(in1, in2);
    gram_k<<<144, 128, GRAM_SMEM>>>();
    dot_k<<<NPAIR, 256>>>();
    finalize_k<<<1, 256>>>(out);
}